// round 1
// baseline (speedup 1.0000x reference)
#include <cuda_runtime.h>
#include <math.h>

#define H 1024
#define W 1024
#define NB 32
#define NPIX (1024*1024)

// Scratch (allocation is forbidden; use device globals)
__device__ float g_x1[33554432];
__device__ float g_i2[33554432];
__device__ float g_t [33554432];

// ---------------------------------------------------------------------------
// K1: fused convA(3x3)+BN+ReLU producing x1, plus reverse (bottom-up) column
// cummax producing i2. One thread per column; rolling shared-memory window.
// ---------------------------------------------------------------------------
#define K1_COLS 128
#define K1_CH 8

__global__ __launch_bounds__(K1_COLS) void k1_convA_colscan(
    const float* __restrict__ x,
    const float* __restrict__ wa, const float* __restrict__ pba,
    const float* __restrict__ pga, const float* __restrict__ pbta,
    const float* __restrict__ pma, const float* __restrict__ pva)
{
    __shared__ float xs[K1_CH + 2][K1_COLS + 2];
    const int tid = threadIdx.x;
    const int c0  = blockIdx.x * K1_COLS;
    const int b   = blockIdx.y;
    const size_t ib = (size_t)b * NPIX;

    float w[9];
#pragma unroll
    for (int i = 0; i < 9; i++) w[i] = __ldg(&wa[i]);
    const float sa = __ldg(pga) * rsqrtf(__ldg(pva) + 1e-5f);
    const float Ba = sa * (__ldg(pba) - __ldg(pma)) + __ldg(pbta);

    float m = 0.0f;                 // x1 = relu(..) >= 0, so 0 is a safe identity
    const int col = c0 + tid;

    for (int k = 0; k < H / K1_CH; k++) {
        const int h0 = H - K1_CH - k * K1_CH;   // chunk rows [h0, h0+K1_CH)
        __syncthreads();
        // load x rows h0-1 .. h0+K1_CH into smem (zero-padded)
        for (int idx = tid; idx < (K1_CH + 2) * (K1_COLS + 2); idx += K1_COLS) {
            int r  = idx / (K1_COLS + 2);
            int cc = idx - r * (K1_COLS + 2);
            int g  = h0 - 1 + r;
            int c  = c0 - 1 + cc;
            float v = 0.0f;
            if ((unsigned)g < H && (unsigned)c < W)
                v = __ldg(&x[ib + (size_t)g * W + c]);
            xs[r][cc] = v;
        }
        __syncthreads();
#pragma unroll
        for (int hh = K1_CH - 1; hh >= 0; hh--) {
            float acc = 0.0f;
#pragma unroll
            for (int ky = 0; ky < 3; ky++)
#pragma unroll
                for (int kx = 0; kx < 3; kx++)
                    acc = fmaf(w[ky * 3 + kx], xs[hh + ky][tid + kx], acc);
            float v = fmaxf(fmaf(sa, acc, Ba), 0.0f);
            m = fmaxf(m, v);
            size_t o = ib + (size_t)(h0 + hh) * W + col;
            g_x1[o] = v;
            g_i2[o] = m;
        }
    }
}

// ---------------------------------------------------------------------------
// K2: reverse row cummax (suffix max along W) of x1, then t = i1 + i2.
// One 256-thread block per row. Warp shfl suffix scans per 32-chunk + carry.
// ---------------------------------------------------------------------------
__global__ __launch_bounds__(256) void k2_rowscan()
{
    __shared__ float srow[1024];
    __shared__ float tots[32];
    __shared__ float carry[32];
    const int tid  = threadIdx.x;
    const int lane = tid & 31;
    const int warp = tid >> 5;
    const size_t base = ((size_t)blockIdx.y * H + blockIdx.x) * W;

#pragma unroll
    for (int j = 0; j < 4; j++) {
        const int q = warp * 4 + j;
        float v = g_x1[base + q * 32 + lane];
#pragma unroll
        for (int off = 1; off < 32; off <<= 1) {
            float o = __shfl_down_sync(0xffffffffu, v, off);
            if (lane < 32 - off) v = fmaxf(v, o);
        }
        srow[q * 32 + lane] = v;
        if (lane == 0) tots[q] = v;
    }
    __syncthreads();
    if (warp == 0) {
        float v = tots[lane];
#pragma unroll
        for (int off = 1; off < 32; off <<= 1) {
            float o = __shfl_down_sync(0xffffffffu, v, off);
            if (lane < 32 - off) v = fmaxf(v, o);
        }
        float c = __shfl_down_sync(0xffffffffu, v, 1);
        if (lane == 31) c = 0.0f;   // values >= 0; 0 is the identity
        carry[lane] = c;
    }
    __syncthreads();
#pragma unroll
    for (int j = 0; j < 4; j++) {
        int e = tid + j * 256;
        float i1 = fmaxf(srow[e], carry[e >> 5]);
        g_t[base + e] = i1 + g_i2[base + e];
    }
}

// ---------------------------------------------------------------------------
// K3: fused tail. Per 64x64 output tile:
//   s   = relu(bnB(conv3(t)) + bnC(conv1(x)))      (68x68, halo 2)
//   u   = relu(bnA(conv3(s)))                      (66x66, halo 1)
//   out = we * relu(conv3(u) + bd) + be            (64x64)
// Vertical 4-strips: stride-1 LDS per warp (conflict-free), coalesced stores.
// ---------------------------------------------------------------------------
#define TS 64
#define TB_STRIDE 71
#define SB_STRIDE 69
#define TB_FLOATS (70 * TB_STRIDE)          // 4970
#define SB_FLOATS (68 * SB_STRIDE + 8)      // 4700 (pad for edge-strip reads)
#define XB_FLOATS (68 * SB_STRIDE)          // 4692
#define K3_SMEM_BYTES ((TB_FLOATS + SB_FLOATS + XB_FLOATS) * 4)

__global__ __launch_bounds__(256) void k3_tail(
    const float* __restrict__ x,
    const float* __restrict__ wb, const float* __restrict__ pbb,
    const float* __restrict__ pgb, const float* __restrict__ pbtb,
    const float* __restrict__ pmb, const float* __restrict__ pvb,
    const float* __restrict__ pwc, const float* __restrict__ pbc,
    const float* __restrict__ pgc, const float* __restrict__ pbtc,
    const float* __restrict__ pmc, const float* __restrict__ pvc,
    const float* __restrict__ wa, const float* __restrict__ pba,
    const float* __restrict__ pga, const float* __restrict__ pbta,
    const float* __restrict__ pma, const float* __restrict__ pva,
    const float* __restrict__ wd, const float* __restrict__ pbd,
    const float* __restrict__ pwe, const float* __restrict__ pbe,
    float* __restrict__ out)
{
    extern __shared__ float sm[];
    float* Tb = sm;                          // t tile  : 70 rows x stride 71
    float* Sb = sm + TB_FLOATS;              // s tile  : 68 rows x stride 69
    float* Xb = Sb + SB_FLOATS;              // x tile  : 68 rows x stride 69
    float* Ub = Tb;                          // u tile reuses Tb: 66 rows x stride 69

    const int tid = threadIdx.x;
    const int r0  = blockIdx.y * TS;
    const int c0  = blockIdx.x * TS;
    const int b   = blockIdx.z;
    const size_t ib = (size_t)b * NPIX;

    const float sbn = __ldg(pgb) * rsqrtf(__ldg(pvb) + 1e-5f);
    const float Bb  = sbn * (__ldg(pbb) - __ldg(pmb)) + __ldg(pbtb);
    const float scn = __ldg(pgc) * rsqrtf(__ldg(pvc) + 1e-5f);
    const float c2x = __ldg(pwc) * scn;
    const float c2b = scn * (__ldg(pbc) - __ldg(pmc)) + __ldg(pbtc);
    const float san = __ldg(pga) * rsqrtf(__ldg(pva) + 1e-5f);
    const float Ba  = san * (__ldg(pba) - __ldg(pma)) + __ldg(pbta);
    const float bdv = __ldg(pbd);
    const float wev = __ldg(pwe);
    const float bev = __ldg(pbe);
    float wbv[9], wav[9], wdv[9];
#pragma unroll
    for (int i = 0; i < 9; i++) {
        wbv[i] = __ldg(&wb[i]);
        wav[i] = __ldg(&wa[i]);
        wdv[i] = __ldg(&wd[i]);
    }

    // Load t tile (halo 3): rows r0-3 .. r0+66
    for (int idx = tid; idx < 70 * 70; idx += 256) {
        int i = idx / 70, j = idx - i * 70;
        int gr = r0 - 3 + i, gc = c0 - 3 + j;
        float v = 0.0f;
        if ((unsigned)gr < H && (unsigned)gc < W) v = g_t[ib + (size_t)gr * W + gc];
        Tb[i * TB_STRIDE + j] = v;
    }
    // Load x tile (halo 2): rows r0-2 .. r0+65
    for (int idx = tid; idx < 68 * 68; idx += 256) {
        int i = idx / 68, j = idx - i * 68;
        int gr = r0 - 2 + i, gc = c0 - 2 + j;
        float v = 0.0f;
        if ((unsigned)gr < H && (unsigned)gc < W) v = __ldg(&x[ib + (size_t)gr * W + gc]);
        Xb[i * SB_STRIDE + j] = v;
    }
    __syncthreads();

    // s tile: 68 rows x 68 cols, vertical strips of 4 (17 strips exact)
    for (int sidx = tid; sidx < 17 * 68; sidx += 256) {
        int j  = sidx % 68;
        int i0 = (sidx / 68) * 4;
        float rv[6][3];
#pragma unroll
        for (int rr = 0; rr < 6; rr++)
#pragma unroll
            for (int kx = 0; kx < 3; kx++)
                rv[rr][kx] = Tb[(i0 + rr) * TB_STRIDE + j + kx];
        int gc = c0 - 2 + j;
#pragma unroll
        for (int ii = 0; ii < 4; ii++) {
            float acc = 0.0f;
#pragma unroll
            for (int ky = 0; ky < 3; ky++)
#pragma unroll
                for (int kx = 0; kx < 3; kx++)
                    acc = fmaf(wbv[ky * 3 + kx], rv[ii + ky][kx], acc);
            int i  = i0 + ii;
            int gr = r0 - 2 + i;
            float s = 0.0f;
            if ((unsigned)gr < H && (unsigned)gc < W) {
                float b2 = fmaf(c2x, Xb[i * SB_STRIDE + j], c2b);
                s = fmaxf(fmaf(sbn, acc, Bb) + b2, 0.0f);
            }
            Sb[i * SB_STRIDE + j] = s;
        }
    }
    __syncthreads();

    // u tile: 66 rows x 66 cols (into Ub = Tb buffer, stride 69)
    for (int sidx = tid; sidx < 17 * 66; sidx += 256) {
        int j  = sidx % 66;
        int i0 = (sidx / 66) * 4;
        float rv[6][3];
#pragma unroll
        for (int rr = 0; rr < 6; rr++) {
            int r = i0 + rr;
#pragma unroll
            for (int kx = 0; kx < 3; kx++)
                rv[rr][kx] = (r < 68) ? Sb[r * SB_STRIDE + j + kx] : 0.0f;
        }
        int gc = c0 - 1 + j;
#pragma unroll
        for (int ii = 0; ii < 4; ii++) {
            int i = i0 + ii;
            if (i < 66) {
                float acc = 0.0f;
#pragma unroll
                for (int ky = 0; ky < 3; ky++)
#pragma unroll
                    for (int kx = 0; kx < 3; kx++)
                        acc = fmaf(wav[ky * 3 + kx], rv[ii + ky][kx], acc);
                int gr = r0 - 1 + i;
                float u = 0.0f;
                if ((unsigned)gr < H && (unsigned)gc < W)
                    u = fmaxf(fmaf(san, acc, Ba), 0.0f);
                Ub[i * SB_STRIDE + j] = u;
            }
        }
    }
    __syncthreads();

    // out: 64 x 64, fused convD + ReLU + convE
    for (int sidx = tid; sidx < 16 * 64; sidx += 256) {
        int j  = sidx % 64;
        int i0 = (sidx / 64) * 4;
        float rv[6][3];
#pragma unroll
        for (int rr = 0; rr < 6; rr++)
#pragma unroll
            for (int kx = 0; kx < 3; kx++)
                rv[rr][kx] = Ub[(i0 + rr) * SB_STRIDE + j + kx];
#pragma unroll
        for (int ii = 0; ii < 4; ii++) {
            float acc = 0.0f;
#pragma unroll
            for (int ky = 0; ky < 3; ky++)
#pragma unroll
                for (int kx = 0; kx < 3; kx++)
                    acc = fmaf(wdv[ky * 3 + kx], rv[ii + ky][kx], acc);
            float v = fmaxf(acc + bdv, 0.0f);
            out[ib + (size_t)(r0 + i0 + ii) * W + (c0 + j)] = fmaf(wev, v, bev);
        }
    }
}

// ---------------------------------------------------------------------------
extern "C" void kernel_launch(void* const* d_in, const int* in_sizes, int n_in,
                              void* d_out, int out_size)
{
    const float* x   = (const float*)d_in[0];
    const float* wa  = (const float*)d_in[1];
    const float* ba  = (const float*)d_in[2];
    const float* ga  = (const float*)d_in[3];
    const float* bta = (const float*)d_in[4];
    const float* ma  = (const float*)d_in[5];
    const float* va  = (const float*)d_in[6];
    const float* wb  = (const float*)d_in[7];
    const float* bb  = (const float*)d_in[8];
    const float* gb  = (const float*)d_in[9];
    const float* btb = (const float*)d_in[10];
    const float* mb  = (const float*)d_in[11];
    const float* vb  = (const float*)d_in[12];
    const float* wc  = (const float*)d_in[13];
    const float* bc  = (const float*)d_in[14];
    const float* gc  = (const float*)d_in[15];
    const float* btc = (const float*)d_in[16];
    const float* mc  = (const float*)d_in[17];
    const float* vc  = (const float*)d_in[18];
    const float* wd  = (const float*)d_in[19];
    const float* bd  = (const float*)d_in[20];
    const float* we  = (const float*)d_in[21];
    const float* be  = (const float*)d_in[22];
    float* out = (float*)d_out;

    cudaFuncSetAttribute(k3_tail, cudaFuncAttributeMaxDynamicSharedMemorySize,
                         K3_SMEM_BYTES);

    dim3 g1(W / K1_COLS, NB);
    k1_convA_colscan<<<g1, K1_COLS>>>(x, wa, ba, ga, bta, ma, va);

    dim3 g2(H, NB);
    k2_rowscan<<<g2, 256>>>();

    dim3 g3(W / TS, H / TS, NB);
    k3_tail<<<g3, 256, K3_SMEM_BYTES>>>(
        x,
        wb, bb, gb, btb, mb, vb,
        wc, bc, gc, btc, mc, vc,
        wa, ba, ga, bta, ma, va,
        wd, bd, we, be,
        out);
}

// round 2
// speedup vs baseline: 1.3806x; 1.3806x over previous
#include <cuda_runtime.h>
#include <math.h>

#define H 1024
#define W 1024
#define NB 32
#define NPIX (1024*1024)
#define SEGS 8
#define SEGH 128

// Scratch (allocation is forbidden; use device globals)
__device__ float g_x1[33554432];
__device__ float g_i2[33554432];          // segment-local bottom-up suffix max
__device__ float g_t [33554432];
__device__ float g_colmax[NB * SEGS * W]; // per (b, seg, col) max
__device__ float g_carry [NB * SEGS * W]; // exclusive carry from segments below

// ---------------------------------------------------------------------------
// K1: fused convA(3x3)+BN+ReLU producing x1, plus segment-local bottom-up
// column cummax. Grid: (W/128, SEGS, NB). 128 threads, one per column.
// ---------------------------------------------------------------------------
#define K1_COLS 128
#define K1_CH 16

__global__ __launch_bounds__(K1_COLS) void k1_convA_colscan(
    const float* __restrict__ x,
    const float* __restrict__ wa, const float* __restrict__ pba,
    const float* __restrict__ pga, const float* __restrict__ pbta,
    const float* __restrict__ pma, const float* __restrict__ pva)
{
    __shared__ float xs[K1_CH + 2][K1_COLS + 2];
    const int tid = threadIdx.x;
    const int c0  = blockIdx.x * K1_COLS;
    const int seg = blockIdx.y;
    const int b   = blockIdx.z;
    const int h0  = seg * SEGH;
    const size_t ib = (size_t)b * NPIX;

    float w[9];
#pragma unroll
    for (int i = 0; i < 9; i++) w[i] = __ldg(&wa[i]);
    const float sa = __ldg(pga) * rsqrtf(__ldg(pva) + 1e-5f);
    const float Ba = sa * (__ldg(pba) - __ldg(pma)) + __ldg(pbta);

    float m = 0.0f;               // relu output >= 0, so 0 is a safe identity
    const int col = c0 + tid;

    for (int k = 0; k < SEGH / K1_CH; k++) {
        const int hb = h0 + SEGH - K1_CH - k * K1_CH;  // chunk rows [hb, hb+CH)
        __syncthreads();
        // load x rows hb-1 .. hb+CH into smem (zero-padded at image edges)
        for (int idx = tid; idx < (K1_CH + 2) * (K1_COLS + 2); idx += K1_COLS) {
            int r  = idx / (K1_COLS + 2);
            int cc = idx - r * (K1_COLS + 2);
            int g  = hb - 1 + r;
            int c  = c0 - 1 + cc;
            float v = 0.0f;
            if ((unsigned)g < H && (unsigned)c < W)
                v = __ldg(&x[ib + (size_t)g * W + c]);
            xs[r][cc] = v;
        }
        __syncthreads();

        // register-rolling 3-row window, bottom-up
        float rA[3], rB[3], rC[3];
#pragma unroll
        for (int kx = 0; kx < 3; kx++) {
            rA[kx] = xs[K1_CH - 1][tid + kx];
            rB[kx] = xs[K1_CH    ][tid + kx];
            rC[kx] = xs[K1_CH + 1][tid + kx];
        }
#pragma unroll
        for (int hh = K1_CH - 1; hh >= 0; hh--) {
            float acc = 0.0f;
#pragma unroll
            for (int kx = 0; kx < 3; kx++) {
                acc = fmaf(w[0 + kx], rA[kx], acc);
                acc = fmaf(w[3 + kx], rB[kx], acc);
                acc = fmaf(w[6 + kx], rC[kx], acc);
            }
            float v = fmaxf(fmaf(sa, acc, Ba), 0.0f);
            m = fmaxf(m, v);
            size_t o = ib + (size_t)(hb + hh) * W + col;
            g_x1[o] = v;
            g_i2[o] = m;
            if (hh > 0) {
#pragma unroll
                for (int kx = 0; kx < 3; kx++) {
                    rC[kx] = rB[kx];
                    rB[kx] = rA[kx];
                    rA[kx] = xs[hh - 1][tid + kx];
                }
            }
        }
    }
    g_colmax[((size_t)b * SEGS + seg) * W + col] = m;
}

// ---------------------------------------------------------------------------
// K1b: exclusive suffix carry across segments (tiny: 1MB)
// ---------------------------------------------------------------------------
__global__ __launch_bounds__(1024) void k1b_carry()
{
    const int b   = blockIdx.x;
    const int col = threadIdx.x;
    float c = 0.0f;
#pragma unroll
    for (int s = SEGS - 1; s >= 0; s--) {
        size_t o = ((size_t)b * SEGS + s) * W + col;
        g_carry[o] = c;
        c = fmaxf(c, g_colmax[o]);
    }
}

// ---------------------------------------------------------------------------
// K2: reverse row cummax (suffix max along W) of x1, then
//     t = i1 + max(i2_local, carry). float4 throughout, 4 elems/thread.
// Grid: (H, NB), 256 threads.
// ---------------------------------------------------------------------------
__global__ __launch_bounds__(256) void k2_rowscan()
{
    __shared__ float wtot[8];
    const int tid  = threadIdx.x;
    const int lane = tid & 31;
    const int warp = tid >> 5;
    const int row  = blockIdx.x;
    const int b    = blockIdx.y;
    const int seg  = row >> 7;
    const size_t base = ((size_t)b * H + row) * W;

    float4 v = ((const float4*)(g_x1 + base))[tid];
    // in-thread suffix max
    float s3 = v.w;
    float s2 = fmaxf(v.z, s3);
    float s1 = fmaxf(v.y, s2);
    float s0 = fmaxf(v.x, s1);
    // warp inclusive suffix scan of thread totals
    float incl = s0;
#pragma unroll
    for (int off = 1; off < 32; off <<= 1) {
        float o = __shfl_down_sync(0xffffffffu, incl, off);
        if (lane < 32 - off) incl = fmaxf(incl, o);
    }
    float rest = __shfl_down_sync(0xffffffffu, incl, 1);
    if (lane == 31) rest = 0.0f;
    if (lane == 0) wtot[warp] = incl;
    __syncthreads();
    float wr = 0.0f;
#pragma unroll
    for (int w2 = 0; w2 < 8; w2++)
        if (w2 > warp) wr = fmaxf(wr, wtot[w2]);
    rest = fmaxf(rest, wr);

    float4 i2 = ((const float4*)(g_i2 + base))[tid];
    size_t cb = ((size_t)b * SEGS + seg) * W;
    float4 cr = ((const float4*)(g_carry + cb))[tid];

    float4 t;
    t.x = fmaxf(s0, rest) + fmaxf(i2.x, cr.x);
    t.y = fmaxf(s1, rest) + fmaxf(i2.y, cr.y);
    t.z = fmaxf(s2, rest) + fmaxf(i2.z, cr.z);
    t.w = fmaxf(s3, rest) + fmaxf(i2.w, cr.w);
    ((float4*)(g_t + base))[tid] = t;
}

// ---------------------------------------------------------------------------
// K3: fused tail. Per 64x64 output tile:
//   s   = relu(bnB(conv3(t)) + bnC(conv1(x)))      (68x68, halo 2; x from gmem)
//   u   = relu(bnA(conv3(s)))                      (66x66, halo 1)
//   out = we * relu(conv3(u) + bd) + be            (64x64)
// ---------------------------------------------------------------------------
#define TS 64
#define TB_STRIDE 71
#define SB_STRIDE 69
#define TB_FLOATS (70 * TB_STRIDE)
#define SB_FLOATS (68 * SB_STRIDE + 8)
#define K3_SMEM_BYTES ((TB_FLOATS + SB_FLOATS) * 4)

__global__ __launch_bounds__(256) void k3_tail(
    const float* __restrict__ x,
    const float* __restrict__ wb, const float* __restrict__ pbb,
    const float* __restrict__ pgb, const float* __restrict__ pbtb,
    const float* __restrict__ pmb, const float* __restrict__ pvb,
    const float* __restrict__ pwc, const float* __restrict__ pbc,
    const float* __restrict__ pgc, const float* __restrict__ pbtc,
    const float* __restrict__ pmc, const float* __restrict__ pvc,
    const float* __restrict__ wa, const float* __restrict__ pba,
    const float* __restrict__ pga, const float* __restrict__ pbta,
    const float* __restrict__ pma, const float* __restrict__ pva,
    const float* __restrict__ wd, const float* __restrict__ pbd,
    const float* __restrict__ pwe, const float* __restrict__ pbe,
    float* __restrict__ out)
{
    extern __shared__ float sm[];
    float* Tb = sm;                 // t tile : 70 rows x stride 71
    float* Sb = sm + TB_FLOATS;     // s tile : 68 rows x stride 69
    float* Ub = Tb;                 // u tile reuses Tb: 66 rows x stride 69

    const int tid = threadIdx.x;
    const int r0  = blockIdx.y * TS;
    const int c0  = blockIdx.x * TS;
    const int b   = blockIdx.z;
    const size_t ib = (size_t)b * NPIX;

    const float sbn = __ldg(pgb) * rsqrtf(__ldg(pvb) + 1e-5f);
    const float Bb  = sbn * (__ldg(pbb) - __ldg(pmb)) + __ldg(pbtb);
    const float scn = __ldg(pgc) * rsqrtf(__ldg(pvc) + 1e-5f);
    const float c2x = __ldg(pwc) * scn;
    const float c2b = scn * (__ldg(pbc) - __ldg(pmc)) + __ldg(pbtc);
    const float san = __ldg(pga) * rsqrtf(__ldg(pva) + 1e-5f);
    const float Ba  = san * (__ldg(pba) - __ldg(pma)) + __ldg(pbta);
    const float bdv = __ldg(pbd);
    const float wev = __ldg(pwe);
    const float bev = __ldg(pbe);
    float wbv[9], wav[9], wdv[9];
#pragma unroll
    for (int i = 0; i < 9; i++) {
        wbv[i] = __ldg(&wb[i]);
        wav[i] = __ldg(&wa[i]);
        wdv[i] = __ldg(&wd[i]);
    }

    // Load t tile (halo 3): rows r0-3 .. r0+66
    for (int idx = tid; idx < 70 * 70; idx += 256) {
        int i = idx / 70, j = idx - i * 70;
        int gr = r0 - 3 + i, gc = c0 - 3 + j;
        float v = 0.0f;
        if ((unsigned)gr < H && (unsigned)gc < W) v = g_t[ib + (size_t)gr * W + gc];
        Tb[i * TB_STRIDE + j] = v;
    }
    __syncthreads();

    // s tile: 68 x 68, vertical strips of 4 (x read directly from gmem)
    for (int sidx = tid; sidx < 17 * 68; sidx += 256) {
        int j  = sidx % 68;
        int i0 = (sidx / 68) * 4;
        float rv[6][3];
#pragma unroll
        for (int rr = 0; rr < 6; rr++)
#pragma unroll
            for (int kx = 0; kx < 3; kx++)
                rv[rr][kx] = Tb[(i0 + rr) * TB_STRIDE + j + kx];
        int gc = c0 - 2 + j;
#pragma unroll
        for (int ii = 0; ii < 4; ii++) {
            float acc = 0.0f;
#pragma unroll
            for (int ky = 0; ky < 3; ky++)
#pragma unroll
                for (int kx = 0; kx < 3; kx++)
                    acc = fmaf(wbv[ky * 3 + kx], rv[ii + ky][kx], acc);
            int i  = i0 + ii;
            int gr = r0 - 2 + i;
            float s = 0.0f;
            if ((unsigned)gr < H && (unsigned)gc < W) {
                float xv = __ldg(&x[ib + (size_t)gr * W + gc]);
                float b2 = fmaf(c2x, xv, c2b);
                s = fmaxf(fmaf(sbn, acc, Bb) + b2, 0.0f);
            }
            Sb[i * SB_STRIDE + j] = s;
        }
    }
    __syncthreads();

    // u tile: 66 x 66 (into Ub = Tb buffer, stride 69)
    for (int sidx = tid; sidx < 17 * 66; sidx += 256) {
        int j  = sidx % 66;
        int i0 = (sidx / 66) * 4;
        float rv[6][3];
#pragma unroll
        for (int rr = 0; rr < 6; rr++) {
            int r = i0 + rr;
#pragma unroll
            for (int kx = 0; kx < 3; kx++)
                rv[rr][kx] = (r < 68) ? Sb[r * SB_STRIDE + j + kx] : 0.0f;
        }
        int gc = c0 - 1 + j;
#pragma unroll
        for (int ii = 0; ii < 4; ii++) {
            int i = i0 + ii;
            if (i < 66) {
                float acc = 0.0f;
#pragma unroll
                for (int ky = 0; ky < 3; ky++)
#pragma unroll
                    for (int kx = 0; kx < 3; kx++)
                        acc = fmaf(wav[ky * 3 + kx], rv[ii + ky][kx], acc);
                int gr = r0 - 1 + i;
                float u = 0.0f;
                if ((unsigned)gr < H && (unsigned)gc < W)
                    u = fmaxf(fmaf(san, acc, Ba), 0.0f);
                Ub[i * SB_STRIDE + j] = u;
            }
        }
    }
    __syncthreads();

    // out: 64 x 64, fused convD + ReLU + convE
    for (int sidx = tid; sidx < 16 * 64; sidx += 256) {
        int j  = sidx % 64;
        int i0 = (sidx / 64) * 4;
        float rv[6][3];
#pragma unroll
        for (int rr = 0; rr < 6; rr++)
#pragma unroll
            for (int kx = 0; kx < 3; kx++)
                rv[rr][kx] = Ub[(i0 + rr) * SB_STRIDE + j + kx];
#pragma unroll
        for (int ii = 0; ii < 4; ii++) {
            float acc = 0.0f;
#pragma unroll
            for (int ky = 0; ky < 3; ky++)
#pragma unroll
                for (int kx = 0; kx < 3; kx++)
                    acc = fmaf(wdv[ky * 3 + kx], rv[ii + ky][kx], acc);
            float v = fmaxf(acc + bdv, 0.0f);
            out[ib + (size_t)(r0 + i0 + ii) * W + (c0 + j)] = fmaf(wev, v, bev);
        }
    }
}

// ---------------------------------------------------------------------------
extern "C" void kernel_launch(void* const* d_in, const int* in_sizes, int n_in,
                              void* d_out, int out_size)
{
    const float* x   = (const float*)d_in[0];
    const float* wa  = (const float*)d_in[1];
    const float* ba  = (const float*)d_in[2];
    const float* ga  = (const float*)d_in[3];
    const float* bta = (const float*)d_in[4];
    const float* ma  = (const float*)d_in[5];
    const float* va  = (const float*)d_in[6];
    const float* wb  = (const float*)d_in[7];
    const float* bb  = (const float*)d_in[8];
    const float* gb  = (const float*)d_in[9];
    const float* btb = (const float*)d_in[10];
    const float* mb  = (const float*)d_in[11];
    const float* vb  = (const float*)d_in[12];
    const float* wc  = (const float*)d_in[13];
    const float* bc  = (const float*)d_in[14];
    const float* gc  = (const float*)d_in[15];
    const float* btc = (const float*)d_in[16];
    const float* mc  = (const float*)d_in[17];
    const float* vc  = (const float*)d_in[18];
    const float* wd  = (const float*)d_in[19];
    const float* bd  = (const float*)d_in[20];
    const float* we  = (const float*)d_in[21];
    const float* be  = (const float*)d_in[22];
    float* out = (float*)d_out;

    cudaFuncSetAttribute(k3_tail, cudaFuncAttributeMaxDynamicSharedMemorySize,
                         K3_SMEM_BYTES);

    dim3 g1(W / K1_COLS, SEGS, NB);
    k1_convA_colscan<<<g1, K1_COLS>>>(x, wa, ba, ga, bta, ma, va);

    k1b_carry<<<NB, 1024>>>();

    dim3 g2(H, NB);
    k2_rowscan<<<g2, 256>>>();

    dim3 g3(W / TS, H / TS, NB);
    k3_tail<<<g3, 256, K3_SMEM_BYTES>>>(
        x,
        wb, bb, gb, btb, mb, vb,
        wc, bc, gc, btc, mc, vc,
        wa, ba, ga, bta, ma, va,
        wd, bd, we, be,
        out);
}

// round 3
// speedup vs baseline: 2.2379x; 1.6210x over previous
#include <cuda_runtime.h>
#include <math.h>

#define H 1024
#define W 1024
#define NB 32
#define NPIX (1024*1024)
#define SEGS 8
#define SEGH 128

// Scratch (allocation is forbidden; use device globals)
__device__ float g_x1[33554432];
__device__ float g_i2[33554432];          // segment-local bottom-up suffix max
__device__ float g_t [33554432];
__device__ float g_colmax[NB * SEGS * W]; // per (b, seg, col) max
__device__ float g_carry [NB * SEGS * W]; // exclusive carry from segments below

// ---------------------------------------------------------------------------
// K1: fused convA(3x3)+BN+ReLU producing x1, plus segment-local bottom-up
// column cummax. Grid: (W/128, SEGS, NB). 128 threads, one per column.
// ---------------------------------------------------------------------------
#define K1_COLS 128
#define K1_CH 16

__global__ __launch_bounds__(K1_COLS) void k1_convA_colscan(
    const float* __restrict__ x,
    const float* __restrict__ wa, const float* __restrict__ pba,
    const float* __restrict__ pga, const float* __restrict__ pbta,
    const float* __restrict__ pma, const float* __restrict__ pva)
{
    __shared__ float xs[K1_CH + 2][K1_COLS + 2];
    const int tid = threadIdx.x;
    const int c0  = blockIdx.x * K1_COLS;
    const int seg = blockIdx.y;
    const int b   = blockIdx.z;
    const int h0  = seg * SEGH;
    const size_t ib = (size_t)b * NPIX;

    float w[9];
#pragma unroll
    for (int i = 0; i < 9; i++) w[i] = __ldg(&wa[i]);
    const float sa = __ldg(pga) * rsqrtf(__ldg(pva) + 1e-5f);
    const float Ba = sa * (__ldg(pba) - __ldg(pma)) + __ldg(pbta);

    float m = 0.0f;               // relu output >= 0, so 0 is a safe identity
    const int col = c0 + tid;

    for (int k = 0; k < SEGH / K1_CH; k++) {
        const int hb = h0 + SEGH - K1_CH - k * K1_CH;  // chunk rows [hb, hb+CH)
        __syncthreads();
        for (int idx = tid; idx < (K1_CH + 2) * (K1_COLS + 2); idx += K1_COLS) {
            int r  = idx / (K1_COLS + 2);
            int cc = idx - r * (K1_COLS + 2);
            int g  = hb - 1 + r;
            int c  = c0 - 1 + cc;
            float v = 0.0f;
            if ((unsigned)g < H && (unsigned)c < W)
                v = __ldg(&x[ib + (size_t)g * W + c]);
            xs[r][cc] = v;
        }
        __syncthreads();

        float rA[3], rB[3], rC[3];
#pragma unroll
        for (int kx = 0; kx < 3; kx++) {
            rA[kx] = xs[K1_CH - 1][tid + kx];
            rB[kx] = xs[K1_CH    ][tid + kx];
            rC[kx] = xs[K1_CH + 1][tid + kx];
        }
#pragma unroll
        for (int hh = K1_CH - 1; hh >= 0; hh--) {
            float acc = 0.0f;
#pragma unroll
            for (int kx = 0; kx < 3; kx++) {
                acc = fmaf(w[0 + kx], rA[kx], acc);
                acc = fmaf(w[3 + kx], rB[kx], acc);
                acc = fmaf(w[6 + kx], rC[kx], acc);
            }
            float v = fmaxf(fmaf(sa, acc, Ba), 0.0f);
            m = fmaxf(m, v);
            size_t o = ib + (size_t)(hb + hh) * W + col;
            g_x1[o] = v;
            g_i2[o] = m;
            if (hh > 0) {
#pragma unroll
                for (int kx = 0; kx < 3; kx++) {
                    rC[kx] = rB[kx];
                    rB[kx] = rA[kx];
                    rA[kx] = xs[hh - 1][tid + kx];
                }
            }
        }
    }
    g_colmax[((size_t)b * SEGS + seg) * W + col] = m;
}

// ---------------------------------------------------------------------------
// K1b: exclusive suffix carry across segments (tiny: 1MB)
// ---------------------------------------------------------------------------
__global__ __launch_bounds__(1024) void k1b_carry()
{
    const int b   = blockIdx.x;
    const int col = threadIdx.x;
    float c = 0.0f;
#pragma unroll
    for (int s = SEGS - 1; s >= 0; s--) {
        size_t o = ((size_t)b * SEGS + s) * W + col;
        g_carry[o] = c;
        c = fmaxf(c, g_colmax[o]);
    }
}

// ---------------------------------------------------------------------------
// K2: reverse row cummax (suffix max along W) of x1, then
//     t = i1 + max(i2_local, carry). float4 throughout.
// ---------------------------------------------------------------------------
__global__ __launch_bounds__(256) void k2_rowscan()
{
    __shared__ float wtot[8];
    const int tid  = threadIdx.x;
    const int lane = tid & 31;
    const int warp = tid >> 5;
    const int row  = blockIdx.x;
    const int b    = blockIdx.y;
    const int seg  = row >> 7;
    const size_t base = ((size_t)b * H + row) * W;

    float4 v = ((const float4*)(g_x1 + base))[tid];
    float s3 = v.w;
    float s2 = fmaxf(v.z, s3);
    float s1 = fmaxf(v.y, s2);
    float s0 = fmaxf(v.x, s1);
    float incl = s0;
#pragma unroll
    for (int off = 1; off < 32; off <<= 1) {
        float o = __shfl_down_sync(0xffffffffu, incl, off);
        if (lane < 32 - off) incl = fmaxf(incl, o);
    }
    float rest = __shfl_down_sync(0xffffffffu, incl, 1);
    if (lane == 31) rest = 0.0f;
    if (lane == 0) wtot[warp] = incl;
    __syncthreads();
    float wr = 0.0f;
#pragma unroll
    for (int w2 = 0; w2 < 8; w2++)
        if (w2 > warp) wr = fmaxf(wr, wtot[w2]);
    rest = fmaxf(rest, wr);

    float4 i2 = ((const float4*)(g_i2 + base))[tid];
    size_t cb = ((size_t)b * SEGS + seg) * W;
    float4 cr = ((const float4*)(g_carry + cb))[tid];

    float4 t;
    t.x = fmaxf(s0, rest) + fmaxf(i2.x, cr.x);
    t.y = fmaxf(s1, rest) + fmaxf(i2.y, cr.y);
    t.z = fmaxf(s2, rest) + fmaxf(i2.z, cr.z);
    t.w = fmaxf(s3, rest) + fmaxf(i2.w, cr.w);
    ((float4*)(g_t + base))[tid] = t;
}

// ---------------------------------------------------------------------------
// K3: fused tail, 4x4 register micro-tiles with float4 shared loads.
//   s   = relu(bnB(conv3(t)) + bnC(conv1(x)))      (68x68, halo 2)
//   u   = relu(bnA(conv3(s)))                      (66x66+pad, halo 1)
//   out = we * relu(conv3(u) + bd) + be            (64x64)
// ---------------------------------------------------------------------------
#define TS 64
#define TBS 72                         // row stride (16B aligned)
#define TB_FLOATS (70 * TBS)           // 5040 floats
#define K3_SMEM_BYTES (2 * TB_FLOATS * 4)

// 3x3 stencil on a 4x4 micro-tile: rolling 6-float row window (2 LDS/row).
__device__ __forceinline__ void stencil4x4(
    const float* __restrict__ buf, int p0, int q0,
    const float wg[9], float acc[4][4])
{
#pragma unroll
    for (int ii = 0; ii < 4; ii++)
#pragma unroll
        for (int jj = 0; jj < 4; jj++) acc[ii][jj] = 0.0f;
#pragma unroll
    for (int r = 0; r < 6; r++) {
        const float* rowp = buf + (p0 + r) * TBS + q0;
        float4 a = *(const float4*)rowp;
        float2 b = *(const float2*)(rowp + 4);
        float rw[6] = {a.x, a.y, a.z, a.w, b.x, b.y};
#pragma unroll
        for (int ky = 0; ky < 3; ky++) {
            int ii = r - ky;
            if (ii >= 0 && ii < 4) {
#pragma unroll
                for (int kx = 0; kx < 3; kx++) {
                    float wk = wg[ky * 3 + kx];
#pragma unroll
                    for (int jj = 0; jj < 4; jj++)
                        acc[ii][jj] = fmaf(wk, rw[jj + kx], acc[ii][jj]);
                }
            }
        }
    }
}

__global__ __launch_bounds__(256) void k3_tail(
    const float* __restrict__ x,
    const float* __restrict__ wb, const float* __restrict__ pbb,
    const float* __restrict__ pgb, const float* __restrict__ pbtb,
    const float* __restrict__ pmb, const float* __restrict__ pvb,
    const float* __restrict__ pwc, const float* __restrict__ pbc,
    const float* __restrict__ pgc, const float* __restrict__ pbtc,
    const float* __restrict__ pmc, const float* __restrict__ pvc,
    const float* __restrict__ wa, const float* __restrict__ pba,
    const float* __restrict__ pga, const float* __restrict__ pbta,
    const float* __restrict__ pma, const float* __restrict__ pva,
    const float* __restrict__ wd, const float* __restrict__ pbd,
    const float* __restrict__ pwe, const float* __restrict__ pbe,
    float* __restrict__ out)
{
    extern __shared__ float sm[];
    float* Tb = sm;                 // t tile : 70 rows x stride 72
    float* Sb = sm + TB_FLOATS;     // s tile : 70 rows x stride 72 (zero pad)
    float* Ub = Tb;                 // u tile reuses Tb

    const int tid = threadIdx.x;
    const int r0  = blockIdx.y * TS;
    const int c0  = blockIdx.x * TS;
    const int b   = blockIdx.z;
    const size_t ib = (size_t)b * NPIX;
    const bool edge = (blockIdx.x == 0) | (blockIdx.x == W/TS - 1) |
                      (blockIdx.y == 0) | (blockIdx.y == H/TS - 1);

    const float sbn = __ldg(pgb) * rsqrtf(__ldg(pvb) + 1e-5f);
    const float Bb  = sbn * (__ldg(pbb) - __ldg(pmb)) + __ldg(pbtb);
    const float scn = __ldg(pgc) * rsqrtf(__ldg(pvc) + 1e-5f);
    const float c2x = __ldg(pwc) * scn;
    const float c2b = scn * (__ldg(pbc) - __ldg(pmc)) + __ldg(pbtc);
    const float san = __ldg(pga) * rsqrtf(__ldg(pva) + 1e-5f);
    const float Ba  = san * (__ldg(pba) - __ldg(pma)) + __ldg(pbta);
    const float bdv = __ldg(pbd);
    const float wev = __ldg(pwe);
    const float bev = __ldg(pbe);

    // Zero Sb (pads must read as 0), load t tile (halo 3, zero outside image)
    for (int idx = tid; idx < TB_FLOATS / 4; idx += 256)
        ((float4*)Sb)[idx] = make_float4(0.f, 0.f, 0.f, 0.f);
    for (int idx = tid; idx < 70 * 70; idx += 256) {
        int i = idx / 70, j = idx - i * 70;
        int gr = r0 - 3 + i, gc = c0 - 3 + j;
        float v = 0.0f;
        if (!edge || ((unsigned)gr < H && (unsigned)gc < W))
            v = g_t[ib + (size_t)gr * W + gc];
        Tb[i * TBS + j] = v;
    }
    __syncthreads();

    // ---- stage s: 68x68 on a 17x17 micro-tile grid ----
    {
        float wg[9];
#pragma unroll
        for (int i = 0; i < 9; i++) wg[i] = __ldg(&wb[i]);
        for (int idx = tid; idx < 289; idx += 256) {
            int pr = idx / 17, pc = idx - pr * 17;
            int p0 = pr * 4, q0 = pc * 4;
            float acc[4][4];
            stencil4x4(Tb, p0, q0, wg, acc);
            int gr0 = r0 - 2 + p0, gc0 = c0 - 2 + q0;
            const float* xp = x + ib + (size_t)gr0 * W + gc0;
            bool full = !edge ||
                ((unsigned)gr0 <= H - 4 && (unsigned)gc0 <= W - 4);
            if (full) {
#pragma unroll
                for (int ii = 0; ii < 4; ii++) {
                    float4 sv;
                    float* o = (float*)&sv;
#pragma unroll
                    for (int jj = 0; jj < 4; jj++) {
                        float xv = __ldg(xp + ii * W + jj);
                        o[jj] = fmaxf(fmaf(sbn, acc[ii][jj], Bb) +
                                      fmaf(c2x, xv, c2b), 0.0f);
                    }
                    *(float4*)&Sb[(p0 + ii) * TBS + q0] = sv;
                }
            } else {
#pragma unroll
                for (int ii = 0; ii < 4; ii++)
#pragma unroll
                    for (int jj = 0; jj < 4; jj++) {
                        int gr = gr0 + ii, gc = gc0 + jj;
                        float s = 0.0f;
                        if ((unsigned)gr < H && (unsigned)gc < W) {
                            float xv = __ldg(&x[ib + (size_t)gr * W + gc]);
                            s = fmaxf(fmaf(sbn, acc[ii][jj], Bb) +
                                      fmaf(c2x, xv, c2b), 0.0f);
                        }
                        Sb[(p0 + ii) * TBS + q0 + jj] = s;
                    }
            }
        }
    }
    __syncthreads();

    // ---- stage u: 68x68 grid (66x66 meaningful), into Ub (=Tb) ----
    {
        float wg[9];
#pragma unroll
        for (int i = 0; i < 9; i++) wg[i] = __ldg(&wa[i]);
        for (int idx = tid; idx < 289; idx += 256) {
            int pr = idx / 17, pc = idx - pr * 17;
            int p0 = pr * 4, q0 = pc * 4;
            float acc[4][4];
            stencil4x4(Sb, p0, q0, wg, acc);
            int gr0 = r0 - 1 + p0, gc0 = c0 - 1 + q0;
            bool full = !edge ||
                ((unsigned)gr0 <= H - 4 && (unsigned)gc0 <= W - 4);
            if (full) {
#pragma unroll
                for (int ii = 0; ii < 4; ii++) {
                    float4 uv;
                    float* o = (float*)&uv;
#pragma unroll
                    for (int jj = 0; jj < 4; jj++)
                        o[jj] = fmaxf(fmaf(san, acc[ii][jj], Ba), 0.0f);
                    *(float4*)&Ub[(p0 + ii) * TBS + q0] = uv;
                }
            } else {
#pragma unroll
                for (int ii = 0; ii < 4; ii++)
#pragma unroll
                    for (int jj = 0; jj < 4; jj++) {
                        int gr = gr0 + ii, gc = gc0 + jj;
                        float u = 0.0f;
                        if ((unsigned)gr < H && (unsigned)gc < W)
                            u = fmaxf(fmaf(san, acc[ii][jj], Ba), 0.0f);
                        Ub[(p0 + ii) * TBS + q0 + jj] = u;
                    }
            }
        }
    }
    __syncthreads();

    // ---- stage out: 64x64, one 4x4 micro-tile per thread ----
    {
        float wg[9];
#pragma unroll
        for (int i = 0; i < 9; i++) wg[i] = __ldg(&wd[i]);
        int i0 = (tid >> 4) * 4, j0 = (tid & 15) * 4;
        float acc[4][4];
        stencil4x4(Ub, i0, j0, wg, acc);
#pragma unroll
        for (int ii = 0; ii < 4; ii++) {
            float4 ov;
            float* o = (float*)&ov;
#pragma unroll
            for (int jj = 0; jj < 4; jj++) {
                float v = fmaxf(acc[ii][jj] + bdv, 0.0f);
                o[jj] = fmaf(wev, v, bev);
            }
            *(float4*)&out[ib + (size_t)(r0 + i0 + ii) * W + (c0 + j0)] = ov;
        }
    }
}

// ---------------------------------------------------------------------------
extern "C" void kernel_launch(void* const* d_in, const int* in_sizes, int n_in,
                              void* d_out, int out_size)
{
    const float* x   = (const float*)d_in[0];
    const float* wa  = (const float*)d_in[1];
    const float* ba  = (const float*)d_in[2];
    const float* ga  = (const float*)d_in[3];
    const float* bta = (const float*)d_in[4];
    const float* ma  = (const float*)d_in[5];
    const float* va  = (const float*)d_in[6];
    const float* wb  = (const float*)d_in[7];
    const float* bb  = (const float*)d_in[8];
    const float* gb  = (const float*)d_in[9];
    const float* btb = (const float*)d_in[10];
    const float* mb  = (const float*)d_in[11];
    const float* vb  = (const float*)d_in[12];
    const float* wc  = (const float*)d_in[13];
    const float* bc  = (const float*)d_in[14];
    const float* gc  = (const float*)d_in[15];
    const float* btc = (const float*)d_in[16];
    const float* mc  = (const float*)d_in[17];
    const float* vc  = (const float*)d_in[18];
    const float* wd  = (const float*)d_in[19];
    const float* bd  = (const float*)d_in[20];
    const float* we  = (const float*)d_in[21];
    const float* be  = (const float*)d_in[22];
    float* out = (float*)d_out;

    cudaFuncSetAttribute(k3_tail, cudaFuncAttributeMaxDynamicSharedMemorySize,
                         K3_SMEM_BYTES);

    dim3 g1(W / K1_COLS, SEGS, NB);
    k1_convA_colscan<<<g1, K1_COLS>>>(x, wa, ba, ga, bta, ma, va);

    k1b_carry<<<NB, 1024>>>();

    dim3 g2(H, NB);
    k2_rowscan<<<g2, 256>>>();

    dim3 g3(W / TS, H / TS, NB);
    k3_tail<<<g3, 256, K3_SMEM_BYTES>>>(
        x,
        wb, bb, gb, btb, mb, vb,
        wc, bc, gc, btc, mc, vc,
        wa, ba, ga, bta, ma, va,
        wd, bd, we, be,
        out);
}

// round 4
// speedup vs baseline: 2.9332x; 1.3107x over previous
#include <cuda_runtime.h>
#include <math.h>

#define H 1024
#define W 1024
#define NB 32
#define NPIX (1024*1024)
#define SEGS 8
#define SEGH 128

// Scratch (allocation is forbidden; use device globals)
__device__ float g_x1[33554432];
__device__ float g_i2[33554432];          // segment-local bottom-up suffix max
__device__ float g_colmax[NB * SEGS * W];
__device__ float g_carry [NB * SEGS * W];

// ---------------------------------------------------------------------------
// K1: fused convA(3x3)+BN+ReLU producing x1, plus segment-local bottom-up
// column cummax. Grid: (W/128, SEGS, NB). 128 threads, one per column.
// ---------------------------------------------------------------------------
#define K1_COLS 128
#define K1_CH 16

__global__ __launch_bounds__(K1_COLS) void k1_convA_colscan(
    const float* __restrict__ x,
    const float* __restrict__ wa, const float* __restrict__ pba,
    const float* __restrict__ pga, const float* __restrict__ pbta,
    const float* __restrict__ pma, const float* __restrict__ pva)
{
    __shared__ float xs[K1_CH + 2][K1_COLS + 2];
    const int tid = threadIdx.x;
    const int c0  = blockIdx.x * K1_COLS;
    const int seg = blockIdx.y;
    const int b   = blockIdx.z;
    const int h0  = seg * SEGH;
    const size_t ib = (size_t)b * NPIX;

    float w[9];
#pragma unroll
    for (int i = 0; i < 9; i++) w[i] = __ldg(&wa[i]);
    const float sa = __ldg(pga) * rsqrtf(__ldg(pva) + 1e-5f);
    const float Ba = sa * (__ldg(pba) - __ldg(pma)) + __ldg(pbta);

    float m = 0.0f;
    const int col = c0 + tid;

    for (int k = 0; k < SEGH / K1_CH; k++) {
        const int hb = h0 + SEGH - K1_CH - k * K1_CH;
        __syncthreads();
        for (int idx = tid; idx < (K1_CH + 2) * (K1_COLS + 2); idx += K1_COLS) {
            int r  = idx / (K1_COLS + 2);
            int cc = idx - r * (K1_COLS + 2);
            int g  = hb - 1 + r;
            int c  = c0 - 1 + cc;
            float v = 0.0f;
            if ((unsigned)g < H && (unsigned)c < W)
                v = __ldg(&x[ib + (size_t)g * W + c]);
            xs[r][cc] = v;
        }
        __syncthreads();

        float rA[3], rB[3], rC[3];
#pragma unroll
        for (int kx = 0; kx < 3; kx++) {
            rA[kx] = xs[K1_CH - 1][tid + kx];
            rB[kx] = xs[K1_CH    ][tid + kx];
            rC[kx] = xs[K1_CH + 1][tid + kx];
        }
#pragma unroll
        for (int hh = K1_CH - 1; hh >= 0; hh--) {
            float acc = 0.0f;
#pragma unroll
            for (int kx = 0; kx < 3; kx++) {
                acc = fmaf(w[0 + kx], rA[kx], acc);
                acc = fmaf(w[3 + kx], rB[kx], acc);
                acc = fmaf(w[6 + kx], rC[kx], acc);
            }
            float v = fmaxf(fmaf(sa, acc, Ba), 0.0f);
            m = fmaxf(m, v);
            size_t o = ib + (size_t)(hb + hh) * W + col;
            g_x1[o] = v;
            g_i2[o] = m;
            if (hh > 0) {
#pragma unroll
                for (int kx = 0; kx < 3; kx++) {
                    rC[kx] = rB[kx];
                    rB[kx] = rA[kx];
                    rA[kx] = xs[hh - 1][tid + kx];
                }
            }
        }
    }
    g_colmax[((size_t)b * SEGS + seg) * W + col] = m;
}

__global__ __launch_bounds__(1024) void k1b_carry()
{
    const int b   = blockIdx.x;
    const int col = threadIdx.x;
    float c = 0.0f;
#pragma unroll
    for (int s = SEGS - 1; s >= 0; s--) {
        size_t o = ((size_t)b * SEGS + s) * W + col;
        g_carry[o] = c;
        c = fmaxf(c, g_colmax[o]);
    }
}

// ---------------------------------------------------------------------------
// K23: merged row-scan + full tail. One block spans the full 1024-wide row
// (256 threads x 4 cols) and rolls down PROWS output rows (+6 pipeline).
// Per row: i1 = reverse row cummax of x1 (block scan), t = i1 + max(i2,carry),
// then incremental-accumulator 3x3 conv chain: s -> u -> out.
// ---------------------------------------------------------------------------
#define PROWS 32
#define PITERS (PROWS + 6)

__device__ __forceinline__ float4 contrib(const float rw[6],
                                          float w0, float w1, float w2)
{
    float4 c;
    c.x = fmaf(w2, rw[2], fmaf(w1, rw[1], w0 * rw[0]));
    c.y = fmaf(w2, rw[3], fmaf(w1, rw[2], w0 * rw[1]));
    c.z = fmaf(w2, rw[4], fmaf(w1, rw[3], w0 * rw[2]));
    c.w = fmaf(w2, rw[5], fmaf(w1, rw[4], w0 * rw[3]));
    return c;
}

// Horizontal halo exchange: out6 = {L, v.x..v.w, R}. Contains a __syncthreads;
// must be called by all threads.
__device__ __forceinline__ void exchange(float4 v, float out6[6],
                                         float* eW, float* eX,
                                         int lane, int warp)
{
    float L = __shfl_up_sync(0xffffffffu, v.w, 1);
    float R = __shfl_down_sync(0xffffffffu, v.x, 1);
    if (lane == 31) eW[warp] = v.w;
    if (lane == 0)  eX[warp] = v.x;
    __syncthreads();
    if (lane == 0)  L = (warp > 0) ? eW[warp - 1] : 0.0f;
    if (lane == 31) R = (warp < 7) ? eX[warp + 1] : 0.0f;
    out6[0] = L; out6[1] = v.x; out6[2] = v.y;
    out6[3] = v.z; out6[4] = v.w; out6[5] = R;
}

__global__ __launch_bounds__(256) void k23_pencil(
    const float* __restrict__ x,
    const float* __restrict__ wb, const float* __restrict__ pbb,
    const float* __restrict__ pgb, const float* __restrict__ pbtb,
    const float* __restrict__ pmb, const float* __restrict__ pvb,
    const float* __restrict__ pwc, const float* __restrict__ pbc,
    const float* __restrict__ pgc, const float* __restrict__ pbtc,
    const float* __restrict__ pmc, const float* __restrict__ pvc,
    const float* __restrict__ wa, const float* __restrict__ pba,
    const float* __restrict__ pga, const float* __restrict__ pbta,
    const float* __restrict__ pma, const float* __restrict__ pva,
    const float* __restrict__ wd, const float* __restrict__ pbd,
    const float* __restrict__ pwe, const float* __restrict__ pbe,
    float* __restrict__ out)
{
    __shared__ float wtot[8];
    __shared__ float eW[3][8], eX[3][8];

    const int tid  = threadIdx.x;
    const int lane = tid & 31;
    const int warp = tid >> 5;
    const int h0   = blockIdx.x * PROWS;
    const int b    = blockIdx.y;
    const size_t ib = (size_t)b * NPIX;
    const int col0 = tid * 4;

    const float sbn = __ldg(pgb) * rsqrtf(__ldg(pvb) + 1e-5f);
    const float Bb  = sbn * (__ldg(pbb) - __ldg(pmb)) + __ldg(pbtb);
    const float scn = __ldg(pgc) * rsqrtf(__ldg(pvc) + 1e-5f);
    const float c2x = __ldg(pwc) * scn;
    const float c2b = scn * (__ldg(pbc) - __ldg(pmc)) + __ldg(pbtc);
    const float san = __ldg(pga) * rsqrtf(__ldg(pva) + 1e-5f);
    const float Ba  = san * (__ldg(pba) - __ldg(pma)) + __ldg(pbta);
    const float bdv = __ldg(pbd);
    const float wev = __ldg(pwe);
    const float bev = __ldg(pbe);
    float wbv[9], wav[9], wdv[9];
#pragma unroll
    for (int i = 0; i < 9; i++) {
        wbv[i] = __ldg(&wb[i]);
        wav[i] = __ldg(&wa[i]);
        wdv[i] = __ldg(&wd[i]);
    }

    const float4 Z4 = make_float4(0.f, 0.f, 0.f, 0.f);
    float4 sAc = Z4, sBc = Z4, uAc = Z4, uBc = Z4, oAc = Z4, oBc = Z4;

    // prefetch registers
    float4 px1 = Z4, pi2 = Z4, pcr = Z4, px = Z4;
    {
        int r = h0 - 3, xr = h0 - 4;
        if ((unsigned)r < H) {
            px1 = *(const float4*)(g_x1 + ib + (size_t)r * W + col0);
            pi2 = *(const float4*)(g_i2 + ib + (size_t)r * W + col0);
            pcr = *(const float4*)(g_carry + ((size_t)b * SEGS + (r >> 7)) * W + col0);
        }
        if ((unsigned)xr < H)
            px = *(const float4*)(x + ib + (size_t)xr * W + col0);
    }

    for (int it = 0; it < PITERS; it++) {
        const int r = h0 - 3 + it;
        float4 cx1 = px1, ci2 = pi2, ccr = pcr, cx = px;
        // prefetch next row
        {
            int rn = r + 1;
            px1 = Z4; pi2 = Z4; pcr = Z4; px = Z4;
            if ((unsigned)rn < H) {
                px1 = *(const float4*)(g_x1 + ib + (size_t)rn * W + col0);
                pi2 = *(const float4*)(g_i2 + ib + (size_t)rn * W + col0);
                pcr = *(const float4*)(g_carry + ((size_t)b * SEGS + (rn >> 7)) * W + col0);
            }
            if ((unsigned)r < H)
                px = *(const float4*)(x + ib + (size_t)r * W + col0);
        }

        // ---- reverse row cummax of x1 (i1), then t ----
        float s3 = cx1.w;
        float s2 = fmaxf(cx1.z, s3);
        float s1 = fmaxf(cx1.y, s2);
        float s0 = fmaxf(cx1.x, s1);
        float incl = s0;
#pragma unroll
        for (int off = 1; off < 32; off <<= 1) {
            float o = __shfl_down_sync(0xffffffffu, incl, off);
            if (lane < 32 - off) incl = fmaxf(incl, o);
        }
        float rest = __shfl_down_sync(0xffffffffu, incl, 1);
        if (lane == 31) rest = 0.0f;
        if (lane == 0) wtot[warp] = incl;
        __syncthreads();                                   // sync A
#pragma unroll
        for (int w2 = 1; w2 < 8; w2++)
            if (w2 > warp) rest = fmaxf(rest, wtot[w2]);

        float4 tv;
        tv.x = fmaxf(s0, rest) + fmaxf(ci2.x, ccr.x);
        tv.y = fmaxf(s1, rest) + fmaxf(ci2.y, ccr.y);
        tv.z = fmaxf(s2, rest) + fmaxf(ci2.z, ccr.z);
        tv.w = fmaxf(s3, rest) + fmaxf(ci2.w, ccr.w);

        float tcur[6];
        exchange(tv, tcur, eW[0], eX[0], lane, warp);      // sync B

        // ---- s stage (row r-1) ----
        {
            float4 c2 = contrib(tcur, wbv[6], wbv[7], wbv[8]);
            float4 c1 = contrib(tcur, wbv[3], wbv[4], wbv[5]);
            float4 c0 = contrib(tcur, wbv[0], wbv[1], wbv[2]);
            float4 sraw;
            sraw.x = sAc.x + c2.x; sraw.y = sAc.y + c2.y;
            sraw.z = sAc.z + c2.z; sraw.w = sAc.w + c2.w;
            sAc.x = sBc.x + c1.x; sAc.y = sBc.y + c1.y;
            sAc.z = sBc.z + c1.z; sAc.w = sBc.w + c1.w;
            sBc = c0;

            const int srow = r - 1;
            const bool sv = (srow >= h0 - 2) && ((unsigned)srow < H);
            float4 sval;
            sval.x = sv ? fmaxf(fmaf(sbn, sraw.x, Bb) + fmaf(c2x, cx.x, c2b), 0.f) : 0.f;
            sval.y = sv ? fmaxf(fmaf(sbn, sraw.y, Bb) + fmaf(c2x, cx.y, c2b), 0.f) : 0.f;
            sval.z = sv ? fmaxf(fmaf(sbn, sraw.z, Bb) + fmaf(c2x, cx.z, c2b), 0.f) : 0.f;
            sval.w = sv ? fmaxf(fmaf(sbn, sraw.w, Bb) + fmaf(c2x, cx.w, c2b), 0.f) : 0.f;

            float scur[6];
            exchange(sval, scur, eW[1], eX[1], lane, warp); // sync C

            // ---- u stage (row r-2) ----
            c2 = contrib(scur, wav[6], wav[7], wav[8]);
            c1 = contrib(scur, wav[3], wav[4], wav[5]);
            c0 = contrib(scur, wav[0], wav[1], wav[2]);
            float4 uraw;
            uraw.x = uAc.x + c2.x; uraw.y = uAc.y + c2.y;
            uraw.z = uAc.z + c2.z; uraw.w = uAc.w + c2.w;
            uAc.x = uBc.x + c1.x; uAc.y = uBc.y + c1.y;
            uAc.z = uBc.z + c1.z; uAc.w = uBc.w + c1.w;
            uBc = c0;

            const int urow = r - 2;
            const bool uv = (urow >= h0 - 1) && ((unsigned)urow < H);
            float4 uval;
            uval.x = uv ? fmaxf(fmaf(san, uraw.x, Ba), 0.f) : 0.f;
            uval.y = uv ? fmaxf(fmaf(san, uraw.y, Ba), 0.f) : 0.f;
            uval.z = uv ? fmaxf(fmaf(san, uraw.z, Ba), 0.f) : 0.f;
            uval.w = uv ? fmaxf(fmaf(san, uraw.w, Ba), 0.f) : 0.f;

            float ucur[6];
            exchange(uval, ucur, eW[2], eX[2], lane, warp); // sync D

            // ---- out stage (row r-3) ----
            c2 = contrib(ucur, wdv[6], wdv[7], wdv[8]);
            c1 = contrib(ucur, wdv[3], wdv[4], wdv[5]);
            c0 = contrib(ucur, wdv[0], wdv[1], wdv[2]);
            float4 oraw;
            oraw.x = oAc.x + c2.x; oraw.y = oAc.y + c2.y;
            oraw.z = oAc.z + c2.z; oraw.w = oAc.w + c2.w;
            oAc.x = oBc.x + c1.x; oAc.y = oBc.y + c1.y;
            oAc.z = oBc.z + c1.z; oAc.w = oBc.w + c1.w;
            oBc = c0;

            const int orow = r - 3;
            if (orow >= h0 && orow < h0 + PROWS) {
                float4 ov;
                ov.x = fmaf(wev, fmaxf(oraw.x + bdv, 0.f), bev);
                ov.y = fmaf(wev, fmaxf(oraw.y + bdv, 0.f), bev);
                ov.z = fmaf(wev, fmaxf(oraw.z + bdv, 0.f), bev);
                ov.w = fmaf(wev, fmaxf(oraw.w + bdv, 0.f), bev);
                *(float4*)(out + ib + (size_t)orow * W + col0) = ov;
            }
        }
    }
}

// ---------------------------------------------------------------------------
extern "C" void kernel_launch(void* const* d_in, const int* in_sizes, int n_in,
                              void* d_out, int out_size)
{
    const float* x   = (const float*)d_in[0];
    const float* wa  = (const float*)d_in[1];
    const float* ba  = (const float*)d_in[2];
    const float* ga  = (const float*)d_in[3];
    const float* bta = (const float*)d_in[4];
    const float* ma  = (const float*)d_in[5];
    const float* va  = (const float*)d_in[6];
    const float* wb  = (const float*)d_in[7];
    const float* bb  = (const float*)d_in[8];
    const float* gb  = (const float*)d_in[9];
    const float* btb = (const float*)d_in[10];
    const float* mb  = (const float*)d_in[11];
    const float* vb  = (const float*)d_in[12];
    const float* wc  = (const float*)d_in[13];
    const float* bc  = (const float*)d_in[14];
    const float* gc  = (const float*)d_in[15];
    const float* btc = (const float*)d_in[16];
    const float* mc  = (const float*)d_in[17];
    const float* vc  = (const float*)d_in[18];
    const float* wd  = (const float*)d_in[19];
    const float* bd  = (const float*)d_in[20];
    const float* we  = (const float*)d_in[21];
    const float* be  = (const float*)d_in[22];
    float* out = (float*)d_out;

    dim3 g1(W / K1_COLS, SEGS, NB);
    k1_convA_colscan<<<g1, K1_COLS>>>(x, wa, ba, ga, bta, ma, va);

    k1b_carry<<<NB, 1024>>>();

    dim3 g23(H / PROWS, NB);
    k23_pencil<<<g23, 256>>>(
        x,
        wb, bb, gb, btb, mb, vb,
        wc, bc, gc, btc, mc, vc,
        wa, ba, ga, bta, ma, va,
        wd, bd, we, be,
        out);
}